// round 15
// baseline (speedup 1.0000x reference)
#include <cuda_runtime.h>
#include <cuda_bf16.h>
#include <cstdint>

// Problem constants
#define B_  8
#define S_  1024
#define D_  1024
#define H_  16
#define DH_ 64

// Scratch buffers (allocation-free rule: __device__ globals)
__device__ float g_qkv[(size_t)B_ * S_ * 3 * D_];           // [B,S,3D] tf32-rounded
__device__ __nv_bfloat16 g_xh[(size_t)B_ * S_ * D_];        // x hi
__device__ __nv_bfloat16 g_xl[(size_t)B_ * S_ * D_];        // x lo
__device__ __nv_bfloat16 g_wqkvh[(size_t)3 * D_ * D_];      // W_qkv^T hi [3D,D]
__device__ __nv_bfloat16 g_wqkvl[(size_t)3 * D_ * D_];      // W_qkv^T lo
__device__ __nv_bfloat16 g_wouth[(size_t)D_ * D_];          // W_out^T hi [D,D]
__device__ __nv_bfloat16 g_woutl[(size_t)D_ * D_];          // W_out^T lo
__device__ __nv_bfloat16 g_attnh[(size_t)B_ * S_ * D_];     // attention out hi
__device__ __nv_bfloat16 g_attnl[(size_t)B_ * S_ * D_];     // attention out lo

// ---------------------------------------------------------------------------
// Helpers
// ---------------------------------------------------------------------------
__device__ __forceinline__ uint32_t f2tf32(float f) {
    uint32_t r;
    asm("cvt.rna.tf32.f32 %0, %1;" : "=r"(r) : "f"(f));
    return r;
}
__device__ __forceinline__ float tf32r(float f) {
    return __uint_as_float(f2tf32(f));
}

__device__ __forceinline__ void mma_tf32(
    float& d0, float& d1, float& d2, float& d3,
    uint32_t a0, uint32_t a1, uint32_t a2, uint32_t a3,
    uint32_t b0, uint32_t b1)
{
    asm volatile(
        "mma.sync.aligned.m16n8k8.row.col.f32.tf32.tf32.f32 "
        "{%0,%1,%2,%3}, {%4,%5,%6,%7}, {%8,%9}, {%0,%1,%2,%3};"
        : "+f"(d0), "+f"(d1), "+f"(d2), "+f"(d3)
        : "r"(a0), "r"(a1), "r"(a2), "r"(a3), "r"(b0), "r"(b1));
}

__device__ __forceinline__ void mma_bf16(
    float& d0, float& d1, float& d2, float& d3,
    uint32_t a0, uint32_t a1, uint32_t a2, uint32_t a3,
    uint32_t b0, uint32_t b1)
{
    asm volatile(
        "mma.sync.aligned.m16n8k16.row.col.f32.bf16.bf16.f32 "
        "{%0,%1,%2,%3}, {%4,%5,%6,%7}, {%8,%9}, {%0,%1,%2,%3};"
        : "+f"(d0), "+f"(d1), "+f"(d2), "+f"(d3)
        : "r"(a0), "r"(a1), "r"(a2), "r"(a3), "r"(b0), "r"(b1));
}

__device__ __forceinline__ void cp_async16(uint32_t s, const void* g) {
    asm volatile("cp.async.cg.shared.global [%0], [%1], 16;" :: "r"(s), "l"(g));
}
__device__ __forceinline__ uint32_t smem_u32(const void* p) {
    return (uint32_t)__cvta_generic_to_shared(p);
}

// Exact split: v == hi + lo + O(2^-16 |v|)
__device__ __forceinline__ void dec2(float v, uint16_t& h, uint16_t& l) {
    __nv_bfloat16 hb = __float2bfloat16_rn(v);
    __nv_bfloat16 lb = __float2bfloat16_rn(v - __bfloat162float(hb));
    h = reinterpret_cast<uint16_t&>(hb);
    l = reinterpret_cast<uint16_t&>(lb);
}

// ---------------------------------------------------------------------------
// Elementwise decompose: fp32 -> (hi, lo) bf16 arrays. float4 granularity.
// ---------------------------------------------------------------------------
__global__ void decompose_kernel(const float* __restrict__ in,
                                 __nv_bfloat16* __restrict__ oh,
                                 __nv_bfloat16* __restrict__ ol, int n4)
{
    int i = blockIdx.x * blockDim.x + threadIdx.x;
    if (i < n4) {
        float4 v = reinterpret_cast<const float4*>(in)[i];
        ushort4 hh, ll;
        dec2(v.x, hh.x, ll.x); dec2(v.y, hh.y, ll.y);
        dec2(v.z, hh.z, ll.z); dec2(v.w, hh.w, ll.w);
        reinterpret_cast<ushort4*>(oh)[i] = hh;
        reinterpret_cast<ushort4*>(ol)[i] = ll;
    }
}

// ---------------------------------------------------------------------------
// Transpose + decompose: in [R,C] fp32 -> oh/ol [C,R] bf16.
// grid (C/32, R/32), block (32, 8).
// ---------------------------------------------------------------------------
__global__ void transpose_dec_kernel(const float* __restrict__ in,
                                     __nv_bfloat16* __restrict__ oh,
                                     __nv_bfloat16* __restrict__ ol,
                                     int R, int C)
{
    __shared__ float tsm[32][33];
    int c0 = blockIdx.x * 32, r0 = blockIdx.y * 32;
    int tx = threadIdx.x, ty = threadIdx.y;
    #pragma unroll
    for (int i = 0; i < 4; ++i)
        tsm[ty + i * 8][tx] = in[(size_t)(r0 + ty + i * 8) * C + c0 + tx];
    __syncthreads();
    #pragma unroll
    for (int i = 0; i < 4; ++i) {
        float v = tsm[tx][ty + i * 8];
        uint16_t h, l;
        dec2(v, h, l);
        size_t o = (size_t)(c0 + ty + i * 8) * R + r0 + tx;
        reinterpret_cast<uint16_t*>(oh)[o] = h;
        reinterpret_cast<uint16_t*>(ol)[o] = l;
    }
}

// ---------------------------------------------------------------------------
// bf16x3 GEMM + bias: C[M,N] = (Ah+Al)[M,K] @ (Bh+Bl)[N,K]^T + bias
// D += Ah*Bh + Ah*Bl + Al*Bh  (Al*Bl ~2^-18, dropped; accuracy > tf32).
// Block 128x128, 4 warps (2x2), warp tile 64x64, BK=32 (2 x k16 steps),
// 2-stage cp.async. Frags are packed bf16-pair LDS.32, conflict-free
// (row stride 40 u16 -> bank (20g+t) mod 32 all-distinct).
// ---------------------------------------------------------------------------
#define AB_STR16 40                     // u16 per row: 32 data + 8 pad
#define TILE_U16 (128 * AB_STR16)       // 5120
#define STAGE_U16 (4 * TILE_U16)        // Ah,Al,Bh,Bl
#define GEMM_SMEM_BYTES (2 * STAGE_U16 * 2)   // 81920

template<bool ROUND_OUT>
__global__ __launch_bounds__(128, 2) void gemm_bf3_kernel(
    const __nv_bfloat16* __restrict__ Ah, const __nv_bfloat16* __restrict__ Al,
    const __nv_bfloat16* __restrict__ Bh, const __nv_bfloat16* __restrict__ Bl,
    const float* __restrict__ bias, float* __restrict__ C,
    int M, int N, int K)
{
    extern __shared__ uint16_t sm16[];

    const int tid  = threadIdx.x;
    const int lane = tid & 31;
    const int warp = tid >> 5;
    const int wm   = warp & 1;
    const int wn   = warp >> 1;
    const int mBase = blockIdx.y * 128;
    const int nBase = blockIdx.x * 128;
    const int g  = lane >> 2;
    const int t  = lane & 3;

    float acc[4][8][4];
    #pragma unroll
    for (int mt = 0; mt < 4; ++mt)
        #pragma unroll
        for (int nt = 0; nt < 8; ++nt)
            #pragma unroll
            for (int f = 0; f < 4; ++f) acc[mt][nt][f] = 0.0f;

    auto loadTile = [&](int buf, int k0) {
        uint16_t* dst = sm16 + buf * STAGE_U16;
        const __nv_bfloat16* srcA[2] = { Ah, Al };
        const __nv_bfloat16* srcB[2] = { Bh, Bl };
        #pragma unroll
        for (int p = 0; p < 2; ++p) {
            uint16_t* d = dst + p * TILE_U16;
            #pragma unroll
            for (int j = 0; j < 4; ++j) {          // 512 chunks of 16B
                int idx = tid + j * 128;
                int r = idx >> 2, c = idx & 3;
                cp_async16(smem_u32(d + r * AB_STR16 + c * 8),
                           srcA[p] + (size_t)(mBase + r) * K + k0 + c * 8);
            }
        }
        #pragma unroll
        for (int p = 0; p < 2; ++p) {
            uint16_t* d = dst + (2 + p) * TILE_U16;
            #pragma unroll
            for (int j = 0; j < 4; ++j) {
                int idx = tid + j * 128;
                int r = idx >> 2, c = idx & 3;
                cp_async16(smem_u32(d + r * AB_STR16 + c * 8),
                           srcB[p] + (size_t)(nBase + r) * K + k0 + c * 8);
            }
        }
        asm volatile("cp.async.commit_group;");
    };

    const int aRow = wm * 64;
    const int bCol = wn * 64;
    const int NIT = K / 32;             // 32

    loadTile(0, 0);

    for (int it = 0; it < NIT; ++it) {
        __syncthreads();   // everyone done reading buffer (it+1)&1 (from it-1)
        if (it + 1 < NIT) {
            loadTile((it + 1) & 1, (it + 1) * 32);
            asm volatile("cp.async.wait_group 1;");   // tile `it` resident
        } else {
            asm volatile("cp.async.wait_group 0;");
        }
        __syncthreads();   // tile `it` visible to all

        const uint32_t* Ah_s = reinterpret_cast<const uint32_t*>(sm16 + (it & 1) * STAGE_U16);
        const uint32_t* Al_s = Ah_s + TILE_U16 / 2;
        const uint32_t* Bh_s = Al_s + TILE_U16 / 2;
        const uint32_t* Bl_s = Bh_s + TILE_U16 / 2;
        // uint32 row stride = 20

        #pragma unroll
        for (int kk = 0; kk < 2; ++kk) {
            const int kb = kk * 8 + t;   // uint32 col: (kk*16 + 2t)/2

            uint32_t ah[4][4], al[4][4];
            #pragma unroll
            for (int mt = 0; mt < 4; ++mt) {
                int r0 = (aRow + mt * 16 + g) * 20;
                int r1 = r0 + 8 * 20;
                ah[mt][0] = Ah_s[r0 + kb];     al[mt][0] = Al_s[r0 + kb];
                ah[mt][1] = Ah_s[r1 + kb];     al[mt][1] = Al_s[r1 + kb];
                ah[mt][2] = Ah_s[r0 + kb + 4]; al[mt][2] = Al_s[r0 + kb + 4];
                ah[mt][3] = Ah_s[r1 + kb + 4]; al[mt][3] = Al_s[r1 + kb + 4];
            }
            uint32_t bh[8][2], bl[8][2];
            #pragma unroll
            for (int nt = 0; nt < 8; ++nt) {
                int n = (bCol + nt * 8 + g) * 20;
                bh[nt][0] = Bh_s[n + kb];      bl[nt][0] = Bl_s[n + kb];
                bh[nt][1] = Bh_s[n + kb + 4];  bl[nt][1] = Bl_s[n + kb + 4];
            }
            #pragma unroll
            for (int mt = 0; mt < 4; ++mt)
                #pragma unroll
                for (int nt = 0; nt < 8; ++nt) {
                    mma_bf16(acc[mt][nt][0], acc[mt][nt][1],
                             acc[mt][nt][2], acc[mt][nt][3],
                             ah[mt][0], ah[mt][1], ah[mt][2], ah[mt][3],
                             bh[nt][0], bh[nt][1]);
                    mma_bf16(acc[mt][nt][0], acc[mt][nt][1],
                             acc[mt][nt][2], acc[mt][nt][3],
                             ah[mt][0], ah[mt][1], ah[mt][2], ah[mt][3],
                             bl[nt][0], bl[nt][1]);
                    mma_bf16(acc[mt][nt][0], acc[mt][nt][1],
                             acc[mt][nt][2], acc[mt][nt][3],
                             al[mt][0], al[mt][1], al[mt][2], al[mt][3],
                             bh[nt][0], bh[nt][1]);
                }
        }
    }

    // ---- epilogue: bias add, float2 stores ----
    #pragma unroll
    for (int mt = 0; mt < 4; ++mt) {
        int r0 = mBase + wm * 64 + mt * 16 + g;
        int r1 = r0 + 8;
        #pragma unroll
        for (int nt = 0; nt < 8; ++nt) {
            int col = nBase + wn * 64 + nt * 8 + t * 2;
            float2 bv = *reinterpret_cast<const float2*>(&bias[col]);
            float2 v0, v1;
            v0.x = acc[mt][nt][0] + bv.x;
            v0.y = acc[mt][nt][1] + bv.y;
            v1.x = acc[mt][nt][2] + bv.x;
            v1.y = acc[mt][nt][3] + bv.y;
            if (ROUND_OUT) {
                v0.x = tf32r(v0.x); v0.y = tf32r(v0.y);
                v1.x = tf32r(v1.x); v1.y = tf32r(v1.y);
            }
            *reinterpret_cast<float2*>(&C[(size_t)r0 * N + col]) = v0;
            *reinterpret_cast<float2*>(&C[(size_t)r1 * N + col]) = v1;
        }
    }
}

// ---------------------------------------------------------------------------
// Tensor-core FlashAttention (tf32, causal): 128-row q-tile, 256 threads,
// 8 warps, cp.async double-buffered K/V (R13 structure). Epilogue emits
// hi/lo bf16 decomposition for the bf16x3 out-projection.
// grid = (8, B*H), q0 = (7-bx)*128.
// ---------------------------------------------------------------------------
#define QP_STRIDE 68
#define K_STRIDE  68
#define V_STRIDE  72
#define QP_F   (128 * QP_STRIDE)
#define KV_K_F (64 * K_STRIDE)
#define KV_V_F (64 * V_STRIDE)
#define STAGE_F (KV_K_F + KV_V_F)
#define ATT_SMEM_BYTES ((QP_F + 2 * STAGE_F) * 4)   // 106496 B

__global__ __launch_bounds__(256, 2) void attention_tc_kernel(
    const float* __restrict__ qkv,
    __nv_bfloat16* __restrict__ attnh, __nv_bfloat16* __restrict__ attnl)
{
    extern __shared__ float sm[];
    float* QP = sm;
    uint32_t* QPu = reinterpret_cast<uint32_t*>(QP);

    const int tid  = threadIdx.x;
    const int lane = tid & 31;
    const int warp = tid >> 5;
    const int g = lane >> 2;
    const int t = lane & 3;
    const int q0 = (7 - blockIdx.x) * 128;
    const int bh = blockIdx.y;
    const int b  = bh >> 4;
    const int h  = bh & 15;

    const float* qbase = qkv + (size_t)b * S_ * 3072 + h * DH_;
    const float* kbase = qbase + D_;
    const float* vbase = qbase + 2 * D_;

    auto load_stage = [&](int buf, int ks) {
        float* Ks = sm + QP_F + buf * STAGE_F;
        float* Vs = Ks + KV_K_F;
        #pragma unroll
        for (int i = 0; i < 4; ++i) {
            int idx = tid + i * 256;
            int r = idx >> 4, c4 = idx & 15;
            cp_async16(smem_u32(Ks + r * K_STRIDE + c4 * 4),
                       kbase + (size_t)(ks + r) * 3072 + c4 * 4);
            cp_async16(smem_u32(Vs + r * V_STRIDE + c4 * 4),
                       vbase + (size_t)(ks + r) * 3072 + c4 * 4);
        }
        asm volatile("cp.async.commit_group;");
    };

    const int nTiles = q0 / 64 + 2;
    load_stage(0, 0);

    #pragma unroll
    for (int i = 0; i < 8; ++i) {
        int idx = tid + i * 256;
        int r = idx >> 4, c4 = idx & 15;
        float4 v = *reinterpret_cast<const float4*>(
            qbase + (size_t)(q0 + r) * 3072 + c4 * 4);
        v.x *= 0.125f; v.y *= 0.125f; v.z *= 0.125f; v.w *= 0.125f;
        *reinterpret_cast<float4*>(QP + r * QP_STRIDE + c4 * 4) = v;
    }
    __syncthreads();

    const int rowA = warp * 16 + g;
    uint32_t qf[8][4];
    #pragma unroll
    for (int kk = 0; kk < 8; ++kk) {
        int c = kk * 8;
        qf[kk][0] = QPu[(rowA    ) * QP_STRIDE + c + t    ];
        qf[kk][1] = QPu[(rowA + 8) * QP_STRIDE + c + t    ];
        qf[kk][2] = QPu[(rowA    ) * QP_STRIDE + c + t + 4];
        qf[kk][3] = QPu[(rowA + 8) * QP_STRIDE + c + t + 4];
    }

    float of[8][4];
    #pragma unroll
    for (int nt = 0; nt < 8; ++nt)
        #pragma unroll
        for (int f = 0; f < 4; ++f) of[nt][f] = 0.0f;
    float m0 = -1e30f, m1 = -1e30f, l0 = 0.0f, l1 = 0.0f;

    for (int kt = 0; kt < nTiles; ++kt) {
        const int ks = kt * 64;
        const int buf = kt & 1;

        __syncthreads();
        if (kt + 1 < nTiles)
            load_stage(buf ^ 1, ks + 64);

        if (kt + 1 < nTiles) asm volatile("cp.async.wait_group 1;");
        else                 asm volatile("cp.async.wait_group 0;");
        __syncthreads();

        const uint32_t* Ksu = reinterpret_cast<const uint32_t*>(sm + QP_F + buf * STAGE_F);
        const uint32_t* Vsu = Ksu + KV_K_F;

        float sv[8][4];
        #pragma unroll
        for (int nt = 0; nt < 8; ++nt) {
            sv[nt][0] = sv[nt][1] = sv[nt][2] = sv[nt][3] = 0.0f;
            #pragma unroll
            for (int kk = 0; kk < 8; ++kk) {
                uint32_t b0 = Ksu[(nt * 8 + g) * K_STRIDE + kk * 8 + t    ];
                uint32_t b1 = Ksu[(nt * 8 + g) * K_STRIDE + kk * 8 + t + 4];
                mma_tf32(sv[nt][0], sv[nt][1], sv[nt][2], sv[nt][3],
                         qf[kk][0], qf[kk][1], qf[kk][2], qf[kk][3], b0, b1);
            }
        }

        if (ks >= q0) {
            int r0 = q0 + rowA, r1 = r0 + 8;
            #pragma unroll
            for (int nt = 0; nt < 8; ++nt) {
                int c0 = ks + nt * 8 + 2 * t, c1 = c0 + 1;
                if (c0 > r0) sv[nt][0] = -1e30f;
                if (c1 > r0) sv[nt][1] = -1e30f;
                if (c0 > r1) sv[nt][2] = -1e30f;
                if (c1 > r1) sv[nt][3] = -1e30f;
            }
        }

        float rx0 = -1e30f, rx1 = -1e30f;
        #pragma unroll
        for (int nt = 0; nt < 8; ++nt) {
            rx0 = fmaxf(rx0, fmaxf(sv[nt][0], sv[nt][1]));
            rx1 = fmaxf(rx1, fmaxf(sv[nt][2], sv[nt][3]));
        }
        rx0 = fmaxf(rx0, __shfl_xor_sync(0xffffffffu, rx0, 1));
        rx0 = fmaxf(rx0, __shfl_xor_sync(0xffffffffu, rx0, 2));
        rx1 = fmaxf(rx1, __shfl_xor_sync(0xffffffffu, rx1, 1));
        rx1 = fmaxf(rx1, __shfl_xor_sync(0xffffffffu, rx1, 2));

        float mn0 = fmaxf(m0, rx0), mn1 = fmaxf(m1, rx1);
        float corr0 = __expf(m0 - mn0), corr1 = __expf(m1 - mn1);
        m0 = mn0; m1 = mn1;

        float ps0 = 0.0f, ps1 = 0.0f;
        #pragma unroll
        for (int nt = 0; nt < 8; ++nt) {
            float p0 = __expf(sv[nt][0] - m0);
            float p1 = __expf(sv[nt][1] - m0);
            float p2 = __expf(sv[nt][2] - m1);
            float p3 = __expf(sv[nt][3] - m1);
            ps0 += p0 + p1;
            ps1 += p2 + p3;
            uint2 w0; w0.x = f2tf32(p0); w0.y = f2tf32(p1);
            uint2 w1; w1.x = f2tf32(p2); w1.y = f2tf32(p3);
            *reinterpret_cast<uint2*>(QPu + (rowA    ) * QP_STRIDE + nt * 8 + 2 * t) = w0;
            *reinterpret_cast<uint2*>(QPu + (rowA + 8) * QP_STRIDE + nt * 8 + 2 * t) = w1;
        }
        ps0 += __shfl_xor_sync(0xffffffffu, ps0, 1);
        ps0 += __shfl_xor_sync(0xffffffffu, ps0, 2);
        ps1 += __shfl_xor_sync(0xffffffffu, ps1, 1);
        ps1 += __shfl_xor_sync(0xffffffffu, ps1, 2);
        l0 = l0 * corr0 + ps0;
        l1 = l1 * corr1 + ps1;

        #pragma unroll
        for (int nt = 0; nt < 8; ++nt) {
            of[nt][0] *= corr0; of[nt][1] *= corr0;
            of[nt][2] *= corr1; of[nt][3] *= corr1;
        }
        __syncwarp();

        #pragma unroll
        for (int kk = 0; kk < 8; ++kk) {
            uint32_t a0 = QPu[(rowA    ) * QP_STRIDE + kk * 8 + t    ];
            uint32_t a1 = QPu[(rowA + 8) * QP_STRIDE + kk * 8 + t    ];
            uint32_t a2 = QPu[(rowA    ) * QP_STRIDE + kk * 8 + t + 4];
            uint32_t a3 = QPu[(rowA + 8) * QP_STRIDE + kk * 8 + t + 4];
            #pragma unroll
            for (int nt = 0; nt < 8; ++nt) {
                uint32_t b0 = Vsu[(kk * 8 + t    ) * V_STRIDE + nt * 8 + g];
                uint32_t b1 = Vsu[(kk * 8 + t + 4) * V_STRIDE + nt * 8 + g];
                mma_tf32(of[nt][0], of[nt][1], of[nt][2], of[nt][3],
                         a0, a1, a2, a3, b0, b1);
            }
        }
    }

    // ---- Normalize and emit hi/lo bf16 decomposition (packed pairs) ----
    const float inv0 = 1.0f / l0;
    const float inv1 = 1.0f / l1;
    const int r0 = q0 + rowA;
    size_t base0 = ((size_t)b * S_ + r0) * D_ + h * DH_;
    size_t base1 = base0 + 8 * (size_t)D_;
    #pragma unroll
    for (int nt = 0; nt < 8; ++nt) {
        int col = nt * 8 + 2 * t;
        uint16_t h0, l0b, h1, l1b, h2, l2b, h3, l3b;
        dec2(of[nt][0] * inv0, h0, l0b);
        dec2(of[nt][1] * inv0, h1, l1b);
        dec2(of[nt][2] * inv1, h2, l2b);
        dec2(of[nt][3] * inv1, h3, l3b);
        *reinterpret_cast<uint32_t*>(&attnh[base0 + col]) = (uint32_t)h0 | ((uint32_t)h1 << 16);
        *reinterpret_cast<uint32_t*>(&attnl[base0 + col]) = (uint32_t)l0b | ((uint32_t)l1b << 16);
        *reinterpret_cast<uint32_t*>(&attnh[base1 + col]) = (uint32_t)h2 | ((uint32_t)h3 << 16);
        *reinterpret_cast<uint32_t*>(&attnl[base1 + col]) = (uint32_t)l2b | ((uint32_t)l3b << 16);
    }
}

// ---------------------------------------------------------------------------
// Launch
// ---------------------------------------------------------------------------
extern "C" void kernel_launch(void* const* d_in, const int* in_sizes, int n_in,
                              void* d_out, int out_size)
{
    (void)in_sizes; (void)n_in; (void)out_size;
    const float* x     = (const float*)d_in[0];
    const float* W_qkv = (const float*)d_in[1];
    const float* b_qkv = (const float*)d_in[2];
    const float* W_out = (const float*)d_in[3];
    const float* b_out = (const float*)d_in[4];
    float* out = (float*)d_out;

    float* qkv;
    __nv_bfloat16 *xh, *xl, *wqkvh, *wqkvl, *wouth, *woutl, *attnh, *attnl;
    cudaGetSymbolAddress((void**)&qkv,   g_qkv);
    cudaGetSymbolAddress((void**)&xh,    g_xh);
    cudaGetSymbolAddress((void**)&xl,    g_xl);
    cudaGetSymbolAddress((void**)&wqkvh, g_wqkvh);
    cudaGetSymbolAddress((void**)&wqkvl, g_wqkvl);
    cudaGetSymbolAddress((void**)&wouth, g_wouth);
    cudaGetSymbolAddress((void**)&woutl, g_woutl);
    cudaGetSymbolAddress((void**)&attnh, g_attnh);
    cudaGetSymbolAddress((void**)&attnl, g_attnl);

    cudaFuncSetAttribute(gemm_bf3_kernel<true>,
                         cudaFuncAttributeMaxDynamicSharedMemorySize, GEMM_SMEM_BYTES);
    cudaFuncSetAttribute(gemm_bf3_kernel<false>,
                         cudaFuncAttributeMaxDynamicSharedMemorySize, GEMM_SMEM_BYTES);
    cudaFuncSetAttribute(attention_tc_kernel,
                         cudaFuncAttributeMaxDynamicSharedMemorySize, ATT_SMEM_BYTES);

    // 0) Decompose x; transpose+decompose weights into [N,K] bf16 hi/lo
    {
        int nx = B_ * S_ * D_ / 4;
        decompose_kernel<<<(nx + 255) / 256, 256>>>(x, xh, xl, nx);
        dim3 blk(32, 8);
        dim3 g1(3 * D_ / 32, D_ / 32);
        transpose_dec_kernel<<<g1, blk>>>(W_qkv, wqkvh, wqkvl, D_, 3 * D_);
        dim3 g2(D_ / 32, D_ / 32);
        transpose_dec_kernel<<<g2, blk>>>(W_out, wouth, woutl, D_, D_);
    }

    // 1) QKV projection (bf16x3) -> g_qkv (tf32-rounded for attention)
    {
        dim3 grid(3 * D_ / 128, (B_ * S_) / 128);   // (24, 64)
        gemm_bf3_kernel<true><<<grid, 128, GEMM_SMEM_BYTES>>>(
            xh, xl, wqkvh, wqkvl, b_qkv, qkv, B_ * S_, 3 * D_, D_);
    }

    // 2) Tensor-core causal flash attention -> attn hi/lo bf16
    {
        dim3 grid(S_ / 128, B_ * H_);               // (8, 128)
        attention_tc_kernel<<<grid, 256, ATT_SMEM_BYTES>>>(qkv, attnh, attnl);
    }

    // 3) Output projection (bf16x3) -> d_out (full fp32)
    {
        dim3 grid(D_ / 128, (B_ * S_) / 128);       // (8, 64)
        gemm_bf3_kernel<false><<<grid, 128, GEMM_SMEM_BYTES>>>(
            attnh, attnl, wouth, woutl, b_out, out, B_ * S_, D_, D_);
    }
}

// round 16
// speedup vs baseline: 2.0559x; 2.0559x over previous
#include <cuda_runtime.h>
#include <cuda_fp16.h>
#include <cstdint>

// Problem constants
#define B_  8
#define S_  1024
#define D_  1024
#define H_  16
#define DH_ 64

// Scratch buffers (allocation-free rule: __device__ globals)
__device__ __half g_qkv[(size_t)B_ * S_ * 3 * D_];     // [B,S,3D] fp16
__device__ __half g_xh[(size_t)B_ * S_ * D_];          // x fp16
__device__ __half g_wqkvh[(size_t)3 * D_ * D_];        // W_qkv^T [3D,D] fp16
__device__ __half g_wouth[(size_t)D_ * D_];            // W_out^T [D,D] fp16
__device__ __half g_attnh[(size_t)B_ * S_ * D_];       // attention out fp16

// ---------------------------------------------------------------------------
// Helpers
// ---------------------------------------------------------------------------
__device__ __forceinline__ void mma_f16(
    float& d0, float& d1, float& d2, float& d3,
    uint32_t a0, uint32_t a1, uint32_t a2, uint32_t a3,
    uint32_t b0, uint32_t b1)
{
    asm volatile(
        "mma.sync.aligned.m16n8k16.row.col.f32.f16.f16.f32 "
        "{%0,%1,%2,%3}, {%4,%5,%6,%7}, {%8,%9}, {%0,%1,%2,%3};"
        : "+f"(d0), "+f"(d1), "+f"(d2), "+f"(d3)
        : "r"(a0), "r"(a1), "r"(a2), "r"(a3), "r"(b0), "r"(b1));
}

__device__ __forceinline__ void cp_async16(uint32_t s, const void* g) {
    asm volatile("cp.async.cg.shared.global [%0], [%1], 16;" :: "r"(s), "l"(g));
}
__device__ __forceinline__ uint32_t smem_u32(const void* p) {
    return (uint32_t)__cvta_generic_to_shared(p);
}
__device__ __forceinline__ uint32_t pack_h2(float a, float b) {
    __half2 h = __floats2half2_rn(a, b);
    return *reinterpret_cast<uint32_t*>(&h);
}

// ---------------------------------------------------------------------------
// fp32 -> fp16 elementwise (float4 granularity)
// ---------------------------------------------------------------------------
__global__ void tohalf_kernel(const float* __restrict__ in,
                              __half* __restrict__ out, int n4)
{
    int i = blockIdx.x * blockDim.x + threadIdx.x;
    if (i < n4) {
        float4 v = reinterpret_cast<const float4*>(in)[i];
        uint2 o;
        o.x = pack_h2(v.x, v.y);
        o.y = pack_h2(v.z, v.w);
        reinterpret_cast<uint2*>(out)[i] = o;
    }
}

// ---------------------------------------------------------------------------
// Transpose fp32 [R,C] -> fp16 [C,R]. grid (C/32, R/32), block (32,8).
// ---------------------------------------------------------------------------
__global__ void transpose_half_kernel(const float* __restrict__ in,
                                      __half* __restrict__ out, int R, int C)
{
    __shared__ float tsm[32][33];
    int c0 = blockIdx.x * 32, r0 = blockIdx.y * 32;
    int tx = threadIdx.x, ty = threadIdx.y;
    #pragma unroll
    for (int i = 0; i < 4; ++i)
        tsm[ty + i * 8][tx] = in[(size_t)(r0 + ty + i * 8) * C + c0 + tx];
    __syncthreads();
    #pragma unroll
    for (int i = 0; i < 4; ++i)
        out[(size_t)(c0 + ty + i * 8) * R + r0 + tx] =
            __float2half_rn(tsm[tx][ty + i * 8]);
}

// ---------------------------------------------------------------------------
// fp16 GEMM + bias: C[M,N] = A[M,K] @ Bt[N,K]^T + bias[N], fp32 accumulate.
// Block 128x128, 4 warps (2x2), warp tile 64x64, BK=32 (2 k16 steps),
// 2-stage cp.async. Fragments are packed fp16-pair LDS.32, conflict-free
// (row stride 40 u16). HALF_OUT: C is __half (rounded); else fp32.
// ---------------------------------------------------------------------------
#define AB_STR16 40                     // u16 per row: 32 data + 8 pad
#define TILE_U16 (128 * AB_STR16)       // 5120
#define STAGE_U16 (2 * TILE_U16)        // A + B
#define GEMM_SMEM_BYTES (2 * STAGE_U16 * 2)   // 40960

template<bool HALF_OUT>
__global__ __launch_bounds__(128, 2) void gemm_f16_kernel(
    const __half* __restrict__ A, const __half* __restrict__ Bt,
    const float* __restrict__ bias, void* __restrict__ Cv,
    int M, int N, int K)
{
    extern __shared__ uint16_t sm16[];

    const int tid  = threadIdx.x;
    const int lane = tid & 31;
    const int warp = tid >> 5;
    const int wm   = warp & 1;
    const int wn   = warp >> 1;
    const int mBase = blockIdx.y * 128;
    const int nBase = blockIdx.x * 128;
    const int g  = lane >> 2;
    const int t  = lane & 3;

    float acc[4][8][4];
    #pragma unroll
    for (int mt = 0; mt < 4; ++mt)
        #pragma unroll
        for (int nt = 0; nt < 8; ++nt)
            #pragma unroll
            for (int f = 0; f < 4; ++f) acc[mt][nt][f] = 0.0f;

    auto loadTile = [&](int buf, int k0) {
        uint16_t* dA = sm16 + buf * STAGE_U16;
        uint16_t* dB = dA + TILE_U16;
        #pragma unroll
        for (int j = 0; j < 4; ++j) {          // A: 128 rows x 4 chunks(16B)
            int idx = tid + j * 128;
            int r = idx >> 2, c = idx & 3;
            cp_async16(smem_u32(dA + r * AB_STR16 + c * 8),
                       A + (size_t)(mBase + r) * K + k0 + c * 8);
        }
        #pragma unroll
        for (int j = 0; j < 4; ++j) {          // B: 128 rows x 4 chunks
            int idx = tid + j * 128;
            int r = idx >> 2, c = idx & 3;
            cp_async16(smem_u32(dB + r * AB_STR16 + c * 8),
                       Bt + (size_t)(nBase + r) * K + k0 + c * 8);
        }
        asm volatile("cp.async.commit_group;");
    };

    const int aRow = wm * 64;
    const int bCol = wn * 64;
    const int NIT = K / 32;             // 32

    loadTile(0, 0);

    for (int it = 0; it < NIT; ++it) {
        __syncthreads();   // everyone done reading buffer (it+1)&1
        if (it + 1 < NIT) {
            loadTile((it + 1) & 1, (it + 1) * 32);
            asm volatile("cp.async.wait_group 1;");   // tile `it` resident
        } else {
            asm volatile("cp.async.wait_group 0;");
        }
        __syncthreads();   // tile `it` visible to all

        const uint32_t* A_s = reinterpret_cast<const uint32_t*>(sm16 + (it & 1) * STAGE_U16);
        const uint32_t* B_s = A_s + TILE_U16 / 2;
        // uint32 row stride = 20

        #pragma unroll
        for (int kk = 0; kk < 2; ++kk) {
            const int kb = kk * 8 + t;

            uint32_t ah[4][4];
            #pragma unroll
            for (int mt = 0; mt < 4; ++mt) {
                int r0 = (aRow + mt * 16 + g) * 20;
                int r1 = r0 + 8 * 20;
                ah[mt][0] = A_s[r0 + kb];
                ah[mt][1] = A_s[r1 + kb];
                ah[mt][2] = A_s[r0 + kb + 4];
                ah[mt][3] = A_s[r1 + kb + 4];
            }
            uint32_t bh[8][2];
            #pragma unroll
            for (int nt = 0; nt < 8; ++nt) {
                int n = (bCol + nt * 8 + g) * 20;
                bh[nt][0] = B_s[n + kb];
                bh[nt][1] = B_s[n + kb + 4];
            }
            #pragma unroll
            for (int mt = 0; mt < 4; ++mt)
                #pragma unroll
                for (int nt = 0; nt < 8; ++nt)
                    mma_f16(acc[mt][nt][0], acc[mt][nt][1],
                            acc[mt][nt][2], acc[mt][nt][3],
                            ah[mt][0], ah[mt][1], ah[mt][2], ah[mt][3],
                            bh[nt][0], bh[nt][1]);
        }
    }

    // ---- epilogue: bias add ----
    #pragma unroll
    for (int mt = 0; mt < 4; ++mt) {
        int r0 = mBase + wm * 64 + mt * 16 + g;
        int r1 = r0 + 8;
        #pragma unroll
        for (int nt = 0; nt < 8; ++nt) {
            int col = nBase + wn * 64 + nt * 8 + t * 2;
            float2 bv = *reinterpret_cast<const float2*>(&bias[col]);
            float x0 = acc[mt][nt][0] + bv.x;
            float y0 = acc[mt][nt][1] + bv.y;
            float x1 = acc[mt][nt][2] + bv.x;
            float y1 = acc[mt][nt][3] + bv.y;
            if (HALF_OUT) {
                __half* Ch = (__half*)Cv;
                *reinterpret_cast<uint32_t*>(&Ch[(size_t)r0 * N + col]) = pack_h2(x0, y0);
                *reinterpret_cast<uint32_t*>(&Ch[(size_t)r1 * N + col]) = pack_h2(x1, y1);
            } else {
                float* Cf = (float*)Cv;
                float2 v0 = make_float2(x0, y0);
                float2 v1 = make_float2(x1, y1);
                *reinterpret_cast<float2*>(&Cf[(size_t)r0 * N + col]) = v0;
                *reinterpret_cast<float2*>(&Cf[(size_t)r1 * N + col]) = v1;
            }
        }
    }
}

// ---------------------------------------------------------------------------
// fp16 FlashAttention (causal): 128-row q-tile, 256 threads, 8 warps,
// cp.async double-buffered K/V. QK and PV via m16n8k16 fp16 MMA, fp32
// accumulate; scale 1/8 applied to fp32 scores (exact). P packs directly
// into A-fragments (no smem round-trip). V B-frags via ldmatrix.x4.trans.
// grid = (8, B*H), q0 = (7-bx)*128.
// ---------------------------------------------------------------------------
#define QS_STR 72                        // u16 stride (36 u32)
#define KS_STR 72
#define VS_STR 72
#define Q_U16   (128 * QS_STR)           // 9216
#define KV_U16  (64 * KS_STR)            // 4608 each
#define STG_U16 (2 * KV_U16)             // K + V
#define ATT_SMEM_BYTES ((Q_U16 + 2 * STG_U16) * 2)   // 55296 B

__global__ __launch_bounds__(256, 2) void attention_f16_kernel(
    const __half* __restrict__ qkv, __half* __restrict__ attnh)
{
    extern __shared__ uint16_t smh[];
    uint16_t* Qs = smh;

    const int tid  = threadIdx.x;
    const int lane = tid & 31;
    const int warp = tid >> 5;          // 0..7
    const int g = lane >> 2;            // 0..7
    const int t = lane & 3;             // 0..3
    const int q0 = (7 - blockIdx.x) * 128;   // heavy tiles first
    const int bh = blockIdx.y;
    const int b  = bh >> 4;
    const int h  = bh & 15;

    const __half* qbase = qkv + (size_t)b * S_ * 3072 + h * DH_;
    const __half* kbase = qbase + D_;
    const __half* vbase = qbase + 2 * D_;

    auto load_stage = [&](int buf, int ks) {
        uint16_t* Ks = smh + Q_U16 + buf * STG_U16;
        uint16_t* Vs = Ks + KV_U16;
        #pragma unroll
        for (int i = 0; i < 2; ++i) {      // K: 64 rows x 8 chunks = 512
            int idx = tid + i * 256;
            int r = idx >> 3, c = idx & 7;
            cp_async16(smem_u32(Ks + r * KS_STR + c * 8),
                       kbase + (size_t)(ks + r) * 3072 + c * 8);
        }
        #pragma unroll
        for (int i = 0; i < 2; ++i) {      // V: 64 rows x 8 chunks
            int idx = tid + i * 256;
            int r = idx >> 3, c = idx & 7;
            cp_async16(smem_u32(Vs + r * VS_STR + c * 8),
                       vbase + (size_t)(ks + r) * 3072 + c * 8);
        }
        asm volatile("cp.async.commit_group;");
    };

    const int nTiles = q0 / 64 + 2;
    load_stage(0, 0);

    // ---- Load Q tile (fp16, unscaled; 1/8 applied to fp32 scores) ----
    #pragma unroll
    for (int i = 0; i < 4; ++i) {          // 128 rows x 8 chunks = 1024
        int idx = tid + i * 256;
        int r = idx >> 3, c = idx & 7;
        *reinterpret_cast<uint4*>(Qs + r * QS_STR + c * 8) =
            *reinterpret_cast<const uint4*>(qbase + (size_t)(q0 + r) * 3072 + c * 8);
    }
    __syncthreads();

    // ---- Q fragments ----
    const int rowA = warp * 16 + g;
    const uint32_t* Qsu = reinterpret_cast<const uint32_t*>(Qs);
    uint32_t qf[4][4];
    #pragma unroll
    for (int kk = 0; kk < 4; ++kk) {
        int r0 = rowA * 36, r1 = (rowA + 8) * 36;
        int kb = kk * 8 + t;
        qf[kk][0] = Qsu[r0 + kb];
        qf[kk][1] = Qsu[r1 + kb];
        qf[kk][2] = Qsu[r0 + kb + 4];
        qf[kk][3] = Qsu[r1 + kb + 4];
    }

    float of[8][4];
    #pragma unroll
    for (int nt = 0; nt < 8; ++nt)
        #pragma unroll
        for (int f = 0; f < 4; ++f) of[nt][f] = 0.0f;
    float m0 = -1e30f, m1 = -1e30f, l0 = 0.0f, l1 = 0.0f;

    for (int kt = 0; kt < nTiles; ++kt) {
        const int ks = kt * 64;
        const int buf = kt & 1;

        __syncthreads();                   // done reading buffer buf^1
        if (kt + 1 < nTiles)
            load_stage(buf ^ 1, ks + 64);

        if (kt + 1 < nTiles) asm volatile("cp.async.wait_group 1;");
        else                 asm volatile("cp.async.wait_group 0;");
        __syncthreads();                   // tile kt visible

        const uint16_t* Ks = smh + Q_U16 + buf * STG_U16;
        const uint16_t* Vs = Ks + KV_U16;
        const uint32_t* Ksu = reinterpret_cast<const uint32_t*>(Ks);

        // ---- S = Q @ K^T (fp32 accum), then * 1/8 ----
        float sv[8][4];
        #pragma unroll
        for (int nt = 0; nt < 8; ++nt) {
            sv[nt][0] = sv[nt][1] = sv[nt][2] = sv[nt][3] = 0.0f;
            #pragma unroll
            for (int kk = 0; kk < 4; ++kk) {
                int n = (nt * 8 + g) * 36;
                int kb = kk * 8 + t;
                uint32_t b0 = Ksu[n + kb];
                uint32_t b1 = Ksu[n + kb + 4];
                mma_f16(sv[nt][0], sv[nt][1], sv[nt][2], sv[nt][3],
                        qf[kk][0], qf[kk][1], qf[kk][2], qf[kk][3], b0, b1);
            }
            sv[nt][0] *= 0.125f; sv[nt][1] *= 0.125f;
            sv[nt][2] *= 0.125f; sv[nt][3] *= 0.125f;
        }

        // ---- Causal mask (only diagonal tiles) ----
        if (ks >= q0) {
            int r0 = q0 + rowA, r1 = r0 + 8;
            #pragma unroll
            for (int nt = 0; nt < 8; ++nt) {
                int c0 = ks + nt * 8 + 2 * t, c1 = c0 + 1;
                if (c0 > r0) sv[nt][0] = -1e30f;
                if (c1 > r0) sv[nt][1] = -1e30f;
                if (c0 > r1) sv[nt][2] = -1e30f;
                if (c1 > r1) sv[nt][3] = -1e30f;
            }
        }

        // ---- Online softmax ----
        float rx0 = -1e30f, rx1 = -1e30f;
        #pragma unroll
        for (int nt = 0; nt < 8; ++nt) {
            rx0 = fmaxf(rx0, fmaxf(sv[nt][0], sv[nt][1]));
            rx1 = fmaxf(rx1, fmaxf(sv[nt][2], sv[nt][3]));
        }
        rx0 = fmaxf(rx0, __shfl_xor_sync(0xffffffffu, rx0, 1));
        rx0 = fmaxf(rx0, __shfl_xor_sync(0xffffffffu, rx0, 2));
        rx1 = fmaxf(rx1, __shfl_xor_sync(0xffffffffu, rx1, 1));
        rx1 = fmaxf(rx1, __shfl_xor_sync(0xffffffffu, rx1, 2));

        float mn0 = fmaxf(m0, rx0), mn1 = fmaxf(m1, rx1);
        float corr0 = __expf(m0 - mn0), corr1 = __expf(m1 - mn1);
        m0 = mn0; m1 = mn1;

        uint32_t ph[8][2];                 // P as fp16 A-fragments
        float ps0 = 0.0f, ps1 = 0.0f;
        #pragma unroll
        for (int nt = 0; nt < 8; ++nt) {
            float p0 = __expf(sv[nt][0] - m0);
            float p1 = __expf(sv[nt][1] - m0);
            float p2 = __expf(sv[nt][2] - m1);
            float p3 = __expf(sv[nt][3] - m1);
            ps0 += p0 + p1;
            ps1 += p2 + p3;
            ph[nt][0] = pack_h2(p0, p1);   // row g
            ph[nt][1] = pack_h2(p2, p3);   // row g+8
        }
        ps0 += __shfl_xor_sync(0xffffffffu, ps0, 1);
        ps0 += __shfl_xor_sync(0xffffffffu, ps0, 2);
        ps1 += __shfl_xor_sync(0xffffffffu, ps1, 1);
        ps1 += __shfl_xor_sync(0xffffffffu, ps1, 2);
        l0 = l0 * corr0 + ps0;
        l1 = l1 * corr1 + ps1;

        #pragma unroll
        for (int nt = 0; nt < 8; ++nt) {
            of[nt][0] *= corr0; of[nt][1] *= corr0;
            of[nt][2] *= corr1; of[nt][3] *= corr1;
        }

        // ---- O += P @ V ;  V B-frags via ldmatrix.x4.trans ----
        const uint32_t vAddrBase = smem_u32(Vs) +
            (uint32_t)(((lane & 15) * VS_STR + 8 * (lane >> 4)) * 2);
        #pragma unroll
        for (int kk = 0; kk < 4; ++kk) {
            uint32_t a0 = ph[2 * kk    ][0];
            uint32_t a1 = ph[2 * kk    ][1];
            uint32_t a2 = ph[2 * kk + 1][0];
            uint32_t a3 = ph[2 * kk + 1][1];
            #pragma unroll
            for (int ntp = 0; ntp < 4; ++ntp) {
                uint32_t addr = vAddrBase +
                    (uint32_t)((kk * 16 * VS_STR + ntp * 16) * 2);
                uint32_t r0, r1, r2, r3;
                asm volatile(
                    "ldmatrix.sync.aligned.m8n8.x4.trans.shared.b16 "
                    "{%0,%1,%2,%3}, [%4];"
                    : "=r"(r0), "=r"(r1), "=r"(r2), "=r"(r3) : "r"(addr));
                mma_f16(of[2 * ntp][0], of[2 * ntp][1],
                        of[2 * ntp][2], of[2 * ntp][3],
                        a0, a1, a2, a3, r0, r1);
                mma_f16(of[2 * ntp + 1][0], of[2 * ntp + 1][1],
                        of[2 * ntp + 1][2], of[2 * ntp + 1][3],
                        a0, a1, a2, a3, r2, r3);
            }
        }
    }

    // ---- Normalize, store fp16 head-regrouped ----
    const float inv0 = 1.0f / l0;
    const float inv1 = 1.0f / l1;
    const int r0 = q0 + rowA;
    size_t base0 = ((size_t)b * S_ + r0) * D_ + h * DH_;
    size_t base1 = base0 + 8 * (size_t)D_;
    #pragma unroll
    for (int nt = 0; nt < 8; ++nt) {
        int col = nt * 8 + 2 * t;
        *reinterpret_cast<uint32_t*>(&attnh[base0 + col]) =
            pack_h2(of[nt][0] * inv0, of[nt][1] * inv0);
        *reinterpret_cast<uint32_t*>(&attnh[base1 + col]) =
            pack_h2(of[nt][2] * inv1, of[nt][3] * inv1);
    }
}

// ---------------------------------------------------------------------------
// Launch
// ---------------------------------------------------------------------------
extern "C" void kernel_launch(void* const* d_in, const int* in_sizes, int n_in,
                              void* d_out, int out_size)
{
    (void)in_sizes; (void)n_in; (void)out_size;
    const float* x     = (const float*)d_in[0];
    const float* W_qkv = (const float*)d_in[1];
    const float* b_qkv = (const float*)d_in[2];
    const float* W_out = (const float*)d_in[3];
    const float* b_out = (const float*)d_in[4];
    float* out = (float*)d_out;

    __half *qkv, *xh, *wqkvh, *wouth, *attnh;
    cudaGetSymbolAddress((void**)&qkv,   g_qkv);
    cudaGetSymbolAddress((void**)&xh,    g_xh);
    cudaGetSymbolAddress((void**)&wqkvh, g_wqkvh);
    cudaGetSymbolAddress((void**)&wouth, g_wouth);
    cudaGetSymbolAddress((void**)&attnh, g_attnh);

    cudaFuncSetAttribute(gemm_f16_kernel<true>,
                         cudaFuncAttributeMaxDynamicSharedMemorySize, GEMM_SMEM_BYTES);
    cudaFuncSetAttribute(gemm_f16_kernel<false>,
                         cudaFuncAttributeMaxDynamicSharedMemorySize, GEMM_SMEM_BYTES);
    cudaFuncSetAttribute(attention_f16_kernel,
                         cudaFuncAttributeMaxDynamicSharedMemorySize, ATT_SMEM_BYTES);

    // 0) Convert x to fp16; transpose weights into [N,K] fp16
    {
        int nx = B_ * S_ * D_ / 4;
        tohalf_kernel<<<(nx + 255) / 256, 256>>>(x, xh, nx);
        dim3 blk(32, 8);
        dim3 g1(3 * D_ / 32, D_ / 32);
        transpose_half_kernel<<<g1, blk>>>(W_qkv, wqkvh, D_, 3 * D_);
        dim3 g2(D_ / 32, D_ / 32);
        transpose_half_kernel<<<g2, blk>>>(W_out, wouth, D_, D_);
    }

    // 1) QKV projection (fp16 MMA, fp32 accum) -> g_qkv fp16
    {
        dim3 grid(3 * D_ / 128, (B_ * S_) / 128);   // (24, 64)
        gemm_f16_kernel<true><<<grid, 128, GEMM_SMEM_BYTES>>>(
            xh, wqkvh, b_qkv, qkv, B_ * S_, 3 * D_, D_);
    }

    // 2) fp16 causal flash attention -> g_attnh fp16
    {
        dim3 grid(S_ / 128, B_ * H_);               // (8, 128)
        attention_f16_kernel<<<grid, 256, ATT_SMEM_BYTES>>>(qkv, attnh);
    }

    // 3) Output projection (fp16 MMA) -> d_out fp32
    {
        dim3 grid(D_ / 128, (B_ * S_) / 128);       // (8, 64)
        gemm_f16_kernel<false><<<grid, 128, GEMM_SMEM_BYTES>>>(
            attnh, wouth, b_out, out, B_ * S_, D_, D_);
    }
}